// round 14
// baseline (speedup 1.0000x reference)
#include <cuda_runtime.h>
#include <cuda_fp16.h>
#include <cstdint>

#define Bd 256
#define Sd 512
#define Cd 64
#define Hd 128
#define Gd 512
#define REC_THREADS 256
#define KR 80
#define QR 20

typedef unsigned long long u64;
typedef unsigned int u32;

// ---------------- device global scratch ----------------
__device__ __half g_xg[(size_t)Sd * Bd * Gd];     // gate preacts, fp16
__device__ __half g_a0[(size_t)Sd * Bd * Cd];     // x, fp16, m-major
__device__ __half g_y1h[(size_t)Sd * Bd * Hd];    // layer-0 h, fp16, m-major
__device__ __half g_w0h[(size_t)Gd * Cd];         // Wih0 fp16
__device__ __half g_w1h[(size_t)Gd * Hd];         // Wih1 fp16
__device__ float  g_bs0[Gd];
__device__ float  g_bs1[Gd];

// ---------------- helpers ----------------
__device__ __forceinline__ void unpack2(u64 v, float& x, float& y) {
    asm("mov.b64 {%0,%1}, %2;" : "=f"(x), "=f"(y) : "l"(v));
}
__device__ __forceinline__ u64 fma2(u64 a, u64 b, u64 c) {
    u64 d; asm("fma.rn.f32x2 %0, %1, %2, %3;" : "=l"(d) : "l"(a), "l"(b), "l"(c)); return d;
}
__device__ __forceinline__ float tanh_fast(float x) {
    float y; asm("tanh.approx.f32 %0, %1;" : "=f"(y) : "f"(x)); return y;
}
__device__ __forceinline__ float hsum2(u64 v) { float a, b; unpack2(v, a, b); return a + b; }
__device__ __forceinline__ void mma_f16(
    float& c0, float& c1, float& c2, float& c3,
    u32 a0, u32 a1, u32 a2, u32 a3, u32 b0, u32 b1)
{
    asm("mma.sync.aligned.m16n8k16.row.col.f32.f16.f16.f32 "
        "{%0,%1,%2,%3}, {%4,%5,%6,%7}, {%8,%9}, {%0,%1,%2,%3};"
        : "+f"(c0), "+f"(c1), "+f"(c2), "+f"(c3)
        : "r"(a0), "r"(a1), "r"(a2), "r"(a3), "r"(b0), "r"(b1));
}
__device__ __forceinline__ void cp16(u32 dst, const void* src) {
    asm volatile("cp.async.cg.shared.global [%0], [%1], 16;" :: "r"(dst), "l"(src));
}
__device__ __forceinline__ u32 smem_u32(const void* p) {
    u32 a; asm("{ .reg .u64 t; cvta.to.shared.u64 t, %1; cvt.u32.u64 %0, t; }" : "=r"(a) : "l"(p));
    return a;
}

// ---------------- prep kernels ----------------
__global__ void prep_x_kernel(const float* __restrict__ x)
{
    int i = blockIdx.x * 256 + threadIdx.x;
    if (i >= Bd * Sd * Cd) return;
    int k = i & (Cd - 1);
    int s = (i >> 6) & (Sd - 1);
    int b = i >> 15;
    g_a0[((size_t)(s * Bd + b)) * Cd + k] = __float2half(x[i]);
}

__global__ void prep_w_kernel(const float* __restrict__ W, const float* __restrict__ b1,
                              const float* __restrict__ b2, __half* __restrict__ wh,
                              float* __restrict__ bsum, int n)
{
    int i = blockIdx.x * 256 + threadIdx.x;
    if (i >= n) return;
    wh[i] = __float2half(W[i]);
    if (i < Gd) bsum[i] = b1[i] + b2[i];
}

// ---------------------------------------------------------------------------
// Pipelined FP16 GEMM (fp32 accum) — unchanged from round 13.
// ---------------------------------------------------------------------------
template <int K>
__global__ __launch_bounds__(256) void gemm_f16_kernel(
    const __half* __restrict__ A, const __half* __restrict__ Wh,
    const float* __restrict__ bsum, __half* __restrict__ out)
{
    constexpr int KC = 32;
    constexpr int NC = K / KC;
    constexpr int SKW = 20;
    constexpr int TBUF = 128 * SKW;

    extern __shared__ u32 sm32[];
    const u32 sb = smem_u32(sm32);

    const int tid = threadIdx.x;
    const int mt  = blockIdx.x;
    const int nt  = blockIdx.y;

    auto fill = [&](int c, int buf) {
        const int k0 = c * KC;
#pragma unroll
        for (int r = 0; r < 2; r++) {
            int task = tid + 256 * r;
            int row = task >> 2, seg = task & 3;
            cp16(sb + (u32)(buf * 2 * TBUF + row * SKW + seg * 4) * 4,
                 (const char*)(A + (size_t)(mt * 128 + row) * K + k0) + seg * 16);
        }
#pragma unroll
        for (int r = 0; r < 2; r++) {
            int task = tid + 256 * r;
            int row = task >> 2, seg = task & 3;
            cp16(sb + (u32)(buf * 2 * TBUF + TBUF + row * SKW + seg * 4) * 4,
                 (const char*)(Wh + (size_t)(nt * 128 + row) * K + k0) + seg * 16);
        }
        asm volatile("cp.async.commit_group;" ::: "memory");
    };

    const int wid  = tid >> 5;
    const int lane = tid & 31;
    const int gID  = lane >> 2;
    const int tig  = lane & 3;
    const int wm   = (wid >> 1) * 32;
    const int wn   = (wid & 1) * 64;

    float c[2][8][4];
#pragma unroll
    for (int i = 0; i < 2; i++)
#pragma unroll
        for (int j = 0; j < 8; j++)
#pragma unroll
            for (int q = 0; q < 4; q++) c[i][j][q] = 0.0f;

    fill(0, 0);

    for (int ch = 0; ch < NC; ch++) {
        if (ch + 1 < NC) {
            fill(ch + 1, (ch + 1) & 1);
            asm volatile("cp.async.wait_group 1;" ::: "memory");
        } else {
            asm volatile("cp.async.wait_group 0;" ::: "memory");
        }
        __syncthreads();

        const u32* As = sm32 + (ch & 1) * 2 * TBUF;
        const u32* Bs = As + TBUF;

#pragma unroll
        for (int ks = 0; ks < KC / 16; ks++) {
            const int kw = ks * 8;
            u32 a[2][4];
#pragma unroll
            for (int mi = 0; mi < 2; mi++) {
                int r = wm + mi * 16 + gID;
                a[mi][0] = As[r * SKW + kw + tig];
                a[mi][1] = As[(r + 8) * SKW + kw + tig];
                a[mi][2] = As[r * SKW + kw + tig + 4];
                a[mi][3] = As[(r + 8) * SKW + kw + tig + 4];
            }
            u32 b[8][2];
#pragma unroll
            for (int ni = 0; ni < 8; ni++) {
                int r = wn + ni * 8 + gID;
                b[ni][0] = Bs[r * SKW + kw + tig];
                b[ni][1] = Bs[r * SKW + kw + tig + 4];
            }
#pragma unroll
            for (int mi = 0; mi < 2; mi++)
#pragma unroll
                for (int ni = 0; ni < 8; ni++)
                    mma_f16(c[mi][ni][0], c[mi][ni][1], c[mi][ni][2], c[mi][ni][3],
                            a[mi][0], a[mi][1], a[mi][2], a[mi][3],
                            b[ni][0], b[ni][1]);
        }
        __syncthreads();
    }

#pragma unroll
    for (int ni = 0; ni < 8; ni++) {
        int g = nt * 128 + wn + ni * 8 + 2 * tig;
        float2 bv = *(const float2*)&bsum[g];
#pragma unroll
        for (int mi = 0; mi < 2; mi++) {
            size_t m = (size_t)mt * 128 + wm + mi * 16 + gID;
            *(__half2*)&out[m * Gd + g] =
                __floats2half2_rn(c[mi][ni][0] + bv.x, c[mi][ni][1] + bv.y);
            *(__half2*)&out[(m + 8) * Gd + g] =
                __floats2half2_rn(c[mi][ni][2] + bv.x, c[mi][ni][3] + bv.y);
        }
    }
}

// ---------------------------------------------------------------------------
// LSTM recurrence v3: k<80 in fp32 registers (FFMA2), k in [80,128) as fp16
// smem weights (48 KB, half the crossbar bytes) with fp16 h shadow and
// __hfma2 partial accumulation (2x 12-term chains per col-batch, converted
// to fp32 once). One barrier per step.
// smem: Wq16 [12 slots][256 thr] 16B quads | hb fp32 [2][2][132] | hf16 [2][2][48]
// ---------------------------------------------------------------------------
#define WQ16_BYTES (12 * 256 * 16)          // 49152
#define HB_OFF     WQ16_BYTES
#define HB_BYTES   (2 * 2 * 132 * 4)        // 4224
#define HF_OFF     (HB_OFF + HB_BYTES)      // 53376 (16B aligned)
#define HF_BYTES   (2 * 2 * 48 * 2)         // 384
#define SMEM_REC   (HF_OFF + HF_BYTES)

template <bool YIMG>
__global__ __launch_bounds__(REC_THREADS, 1) void lstm_rec_kernel(
    const __half* __restrict__ xg, const float* __restrict__ Whh,
    __half* __restrict__ y_img, float* __restrict__ y_last)
{
    extern __shared__ char smraw[];
    ulonglong2* Wq16 = (ulonglong2*)smraw;
    float* hb  = (float*)(smraw + HB_OFF);
    __half* hf = (__half*)(smraw + HF_OFF);

    const int t = threadIdx.x;
    const int u = t >> 1;
    const int p = t & 1;
    const int col0 = p * 128 + u;
    const int col1 = 256 + p * 128 + u;
    const int b0 = blockIdx.x * 2;

    // register weights: k in [0, 80) for both columns (fp32 pairs)
    u64 wA[2 * QR], wB[2 * QR];
    {
        const u64* rowA = (const u64*)(Whh + (size_t)col0 * Hd);
        const u64* rowB = (const u64*)(Whh + (size_t)col1 * Hd);
#pragma unroll
        for (int j = 0; j < 2 * QR; j++) { wA[j] = rowA[j]; wB[j] = rowB[j]; }
    }
    // fp16 smem weights: k in [80,128), 6 quads of 8 halves per column
#pragma unroll
    for (int q = 0; q < 6; q++) {
        union { ulonglong2 v; __half h[8]; } pk0, pk1;
#pragma unroll
        for (int j = 0; j < 8; j++) {
            pk0.h[j] = __float2half(Whh[(size_t)col0 * Hd + KR + 8 * q + j]);
            pk1.h[j] = __float2half(Whh[(size_t)col1 * Hd + KR + 8 * q + j]);
        }
        Wq16[q * 256 + t]       = pk0.v;
        Wq16[(6 + q) * 256 + t] = pk1.v;
    }
    for (int i = t; i < (HB_BYTES / 4); i += REC_THREADS) hb[i] = 0.0f;
    if (t < HF_BYTES / 4) ((u32*)hf)[t] = 0;

    float c = 0.0f;
    __syncthreads();

    __half xh00 = xg[(size_t)(b0)*Gd + col0];
    __half xh01 = xg[(size_t)(b0 + 1) * Gd + col0];
    __half xh10 = xg[(size_t)(b0)*Gd + col1];
    __half xh11 = xg[(size_t)(b0 + 1) * Gd + col1];

    for (int s = 0; s < Sd; s++) {
        __half nh00, nh01, nh10, nh11;
        if (s + 1 < Sd) {
            size_t base = (size_t)(s + 1) * Bd + b0;
            nh00 = xg[base * Gd + col0];
            nh01 = xg[(base + 1) * Gd + col0];
            nh10 = xg[base * Gd + col1];
            nh11 = xg[(base + 1) * Gd + col1];
        } else {
            nh00 = nh01 = nh10 = nh11 = __half(0.0f);
        }
        const int ph = s & 1;
        const ulonglong2* hq0 = (const ulonglong2*)(hb + (ph * 2 + 0) * 132);
        const ulonglong2* hq1 = (const ulonglong2*)(hb + (ph * 2 + 1) * 132);

        // ---- k < 80 : fp32 register weights ----
        u64 a00e = 0, a00o = 0, a01e = 0, a01o = 0;
        u64 a10e = 0, a10o = 0, a11e = 0, a11o = 0;
#pragma unroll
        for (int j = 0; j < QR; j++) {
            ulonglong2 hA = hq0[j], hB = hq1[j];
            a00e = fma2(wA[2 * j], hA.x, a00e);
            a00o = fma2(wA[2 * j + 1], hA.y, a00o);
            a01e = fma2(wA[2 * j], hB.x, a01e);
            a01o = fma2(wA[2 * j + 1], hB.y, a01o);
            a10e = fma2(wB[2 * j], hA.x, a10e);
            a10o = fma2(wB[2 * j + 1], hA.y, a10o);
            a11e = fma2(wB[2 * j], hB.x, a11e);
            a11o = fma2(wB[2 * j + 1], hB.y, a11o);
        }

        // ---- k in [80,128) : fp16 smem weights, hfma2 chains ----
        const __half* hfA = hf + (ph * 2 + 0) * 48;
        const __half* hfB = hf + (ph * 2 + 1) * 48;
        __half2 ac00a = __half2(0, 0), ac00b = __half2(0, 0);
        __half2 ac01a = __half2(0, 0), ac01b = __half2(0, 0);
        __half2 ac10a = __half2(0, 0), ac10b = __half2(0, 0);
        __half2 ac11a = __half2(0, 0), ac11b = __half2(0, 0);
#pragma unroll
        for (int q = 0; q < 6; q++) {
            ulonglong2 w0q = Wq16[q * 256 + t];
            ulonglong2 w1q = Wq16[(6 + q) * 256 + t];
            ulonglong2 h0q = *(const ulonglong2*)(hfA + q * 8);
            ulonglong2 h1q = *(const ulonglong2*)(hfB + q * 8);
            const __half2* w0 = (const __half2*)&w0q;
            const __half2* w1 = (const __half2*)&w1q;
            const __half2* hA = (const __half2*)&h0q;
            const __half2* hB = (const __half2*)&h1q;
            if (q < 3) {
#pragma unroll
                for (int j = 0; j < 4; j++) {
                    ac00a = __hfma2(w0[j], hA[j], ac00a);
                    ac01a = __hfma2(w0[j], hB[j], ac01a);
                    ac10a = __hfma2(w1[j], hA[j], ac10a);
                    ac11a = __hfma2(w1[j], hB[j], ac11a);
                }
            } else {
#pragma unroll
                for (int j = 0; j < 4; j++) {
                    ac00b = __hfma2(w0[j], hA[j], ac00b);
                    ac01b = __hfma2(w0[j], hB[j], ac01b);
                    ac10b = __hfma2(w1[j], hA[j], ac10b);
                    ac11b = __hfma2(w1[j], hB[j], ac11b);
                }
            }
        }
        float2 f0a = __half22float2(ac00a), f0b = __half22float2(ac00b);
        float2 f1a = __half22float2(ac01a), f1b = __half22float2(ac01b);
        float2 f2a = __half22float2(ac10a), f2b = __half22float2(ac10b);
        float2 f3a = __half22float2(ac11a), f3b = __half22float2(ac11b);

        float p00 = __half2float(xh00) + hsum2(a00e) + hsum2(a00o) + (f0a.x + f0a.y) + (f0b.x + f0b.y);
        float p01 = __half2float(xh01) + hsum2(a01e) + hsum2(a01o) + (f1a.x + f1a.y) + (f1b.x + f1b.y);
        float p10 = __half2float(xh10) + hsum2(a10e) + hsum2(a10o) + (f2a.x + f2a.y) + (f2b.x + f2b.y);
        float p11 = __half2float(xh11) + hsum2(a11e) + hsum2(a11o) + (f3a.x + f3a.y) + (f3b.x + f3b.y);

        float v00 = fmaf(0.5f, tanh_fast(0.5f * p00), 0.5f);
        float v01 = fmaf(0.5f, tanh_fast(0.5f * p01), 0.5f);
        float a10s = (p == 0) ? p10 : 0.5f * p10;
        float a11s = (p == 0) ? p11 : 0.5f * p11;
        float t10 = tanh_fast(a10s);
        float t11 = tanh_fast(a11s);
        float v10 = (p == 0) ? t10 : fmaf(0.5f, t10, 0.5f);
        float v11 = (p == 0) ? t11 : fmaf(0.5f, t11, 0.5f);

        float send1 = (p == 0) ? v01 : v00;
        float send2 = (p == 0) ? v11 : v10;
        float got1 = __shfl_xor_sync(0xffffffffu, send1, 1);
        float got2 = __shfl_xor_sync(0xffffffffu, send2, 1);

        float iv = (p == 0) ? v00 : got1;
        float fv = (p == 0) ? got1 : v01;
        float gv = (p == 0) ? v10 : got2;
        float ov = (p == 0) ? got2 : v11;

        c = fmaf(fv, c, iv * gv);
        float hn = ov * tanh_fast(c);

        hb[((ph ^ 1) * 2 + p) * 132 + u] = hn;
        if (u >= KR) {   // fp16 shadow of h[80:128) for next step
            hf[((ph ^ 1) * 2 + p) * 48 + (u - KR)] = __float2half(hn);
        }
        if (YIMG) {
            y_img[((size_t)s * Bd + b0 + p) * Hd + u] = __float2half(hn);
        } else if (s == Sd - 1) {
            y_last[(size_t)(b0 + p) * Hd + u] = hn;
        }

        xh00 = nh00; xh01 = nh01; xh10 = nh10; xh11 = nh11;
        __syncthreads();
    }
}

// ---------------------------------------------------------------------------
extern "C" void kernel_launch(void* const* d_in, const int* in_sizes, int n_in,
                              void* d_out, int out_size)
{
    const float* x    = (const float*)d_in[0];
    const float* Wih0 = (const float*)d_in[1];
    const float* Whh0 = (const float*)d_in[2];
    const float* bih0 = (const float*)d_in[3];
    const float* bhh0 = (const float*)d_in[4];
    const float* Wih1 = (const float*)d_in[5];
    const float* Whh1 = (const float*)d_in[6];
    const float* bih1 = (const float*)d_in[7];
    const float* bhh1 = (const float*)d_in[8];
    float* out = (float*)d_out;

    __half *xg, *a0, *y1h, *w0h, *w1h;
    float *bs0, *bs1;
    cudaGetSymbolAddress((void**)&xg, g_xg);
    cudaGetSymbolAddress((void**)&a0, g_a0);
    cudaGetSymbolAddress((void**)&y1h, g_y1h);
    cudaGetSymbolAddress((void**)&w0h, g_w0h);
    cudaGetSymbolAddress((void**)&w1h, g_w1h);
    cudaGetSymbolAddress((void**)&bs0, g_bs0);
    cudaGetSymbolAddress((void**)&bs1, g_bs1);

    const int smem_gemm = 2 * 2 * 128 * 20 * 4;   // 40960 B

    cudaFuncSetAttribute((const void*)gemm_f16_kernel<Cd>,
                         cudaFuncAttributeMaxDynamicSharedMemorySize, smem_gemm);
    cudaFuncSetAttribute((const void*)gemm_f16_kernel<Hd>,
                         cudaFuncAttributeMaxDynamicSharedMemorySize, smem_gemm);
    cudaFuncSetAttribute((const void*)lstm_rec_kernel<true>,
                         cudaFuncAttributeMaxDynamicSharedMemorySize, SMEM_REC);
    cudaFuncSetAttribute((const void*)lstm_rec_kernel<false>,
                         cudaFuncAttributeMaxDynamicSharedMemorySize, SMEM_REC);

    prep_x_kernel<<<(Bd * Sd * Cd + 255) / 256, 256>>>(x);
    prep_w_kernel<<<(Gd * Cd + 255) / 256, 256>>>(Wih0, bih0, bhh0, w0h, bs0, Gd * Cd);
    prep_w_kernel<<<(Gd * Hd + 255) / 256, 256>>>(Wih1, bih1, bhh1, w1h, bs1, Gd * Hd);

    dim3 ggrid((Sd * Bd) / 128, Gd / 128);

    // layer 0
    gemm_f16_kernel<Cd><<<ggrid, 256, smem_gemm>>>(a0, w0h, bs0, xg);
    lstm_rec_kernel<true><<<Bd / 2, REC_THREADS, SMEM_REC>>>(xg, Whh0, y1h, nullptr);

    // layer 1
    gemm_f16_kernel<Hd><<<ggrid, 256, smem_gemm>>>(y1h, w1h, bs1, xg);
    lstm_rec_kernel<false><<<Bd / 2, REC_THREADS, SMEM_REC>>>(xg, Whh1, nullptr, out);
}

// round 15
// speedup vs baseline: 1.1061x; 1.1061x over previous
#include <cuda_runtime.h>
#include <cuda_fp16.h>
#include <cstdint>

#define Bd 256
#define Sd 512
#define Cd 64
#define Hd 128
#define Gd 512
#define REC_THREADS 256

typedef unsigned long long u64;
typedef unsigned int u32;

// ---------------- device global scratch ----------------
__device__ __half g_xg[(size_t)Sd * Bd * Gd];     // gate preacts, fp16
__device__ __half g_a0[(size_t)Sd * Bd * Cd];     // x, fp16, m-major
__device__ __half g_y1h[(size_t)Sd * Bd * Hd];    // layer-0 h, fp16, m-major
__device__ __half g_w0h[(size_t)Gd * Cd];         // Wih0 fp16
__device__ __half g_w1h[(size_t)Gd * Hd];         // Wih1 fp16
__device__ float  g_bs0[Gd];
__device__ float  g_bs1[Gd];

// ---------------- helpers ----------------
__device__ __forceinline__ float tanh_fast(float x) {
    float y; asm("tanh.approx.f32 %0, %1;" : "=f"(y) : "f"(x)); return y;
}
__device__ __forceinline__ void mma_f16(
    float& c0, float& c1, float& c2, float& c3,
    u32 a0, u32 a1, u32 a2, u32 a3, u32 b0, u32 b1)
{
    asm("mma.sync.aligned.m16n8k16.row.col.f32.f16.f16.f32 "
        "{%0,%1,%2,%3}, {%4,%5,%6,%7}, {%8,%9}, {%0,%1,%2,%3};"
        : "+f"(c0), "+f"(c1), "+f"(c2), "+f"(c3)
        : "r"(a0), "r"(a1), "r"(a2), "r"(a3), "r"(b0), "r"(b1));
}
__device__ __forceinline__ void cp16(u32 dst, const void* src) {
    asm volatile("cp.async.cg.shared.global [%0], [%1], 16;" :: "r"(dst), "l"(src));
}
__device__ __forceinline__ u32 smem_u32(const void* p) {
    u32 a; asm("{ .reg .u64 t; cvta.to.shared.u64 t, %1; cvt.u32.u64 %0, t; }" : "=r"(a) : "l"(p));
    return a;
}

// ---------------- prep kernels ----------------
__global__ void prep_x_kernel(const float* __restrict__ x)
{
    int i = blockIdx.x * 256 + threadIdx.x;
    if (i >= Bd * Sd * Cd) return;
    int k = i & (Cd - 1);
    int s = (i >> 6) & (Sd - 1);
    int b = i >> 15;
    g_a0[((size_t)(s * Bd + b)) * Cd + k] = __float2half(x[i]);
}

__global__ void prep_w_kernel(const float* __restrict__ W, const float* __restrict__ b1,
                              const float* __restrict__ b2, __half* __restrict__ wh,
                              float* __restrict__ bsum, int n)
{
    int i = blockIdx.x * 256 + threadIdx.x;
    if (i >= n) return;
    wh[i] = __float2half(W[i]);
    if (i < Gd) bsum[i] = b1[i] + b2[i];
}

// ---------------------------------------------------------------------------
// Pipelined FP16 GEMM (fp32 accum) — unchanged (round-13 proven).
// ---------------------------------------------------------------------------
template <int K>
__global__ __launch_bounds__(256) void gemm_f16_kernel(
    const __half* __restrict__ A, const __half* __restrict__ Wh,
    const float* __restrict__ bsum, __half* __restrict__ out)
{
    constexpr int KC = 32;
    constexpr int NC = K / KC;
    constexpr int SKW = 20;
    constexpr int TBUF = 128 * SKW;

    extern __shared__ u32 sm32[];
    const u32 sb = smem_u32(sm32);

    const int tid = threadIdx.x;
    const int mt  = blockIdx.x;
    const int nt  = blockIdx.y;

    auto fill = [&](int c, int buf) {
        const int k0 = c * KC;
#pragma unroll
        for (int r = 0; r < 2; r++) {
            int task = tid + 256 * r;
            int row = task >> 2, seg = task & 3;
            cp16(sb + (u32)(buf * 2 * TBUF + row * SKW + seg * 4) * 4,
                 (const char*)(A + (size_t)(mt * 128 + row) * K + k0) + seg * 16);
        }
#pragma unroll
        for (int r = 0; r < 2; r++) {
            int task = tid + 256 * r;
            int row = task >> 2, seg = task & 3;
            cp16(sb + (u32)(buf * 2 * TBUF + TBUF + row * SKW + seg * 4) * 4,
                 (const char*)(Wh + (size_t)(nt * 128 + row) * K + k0) + seg * 16);
        }
        asm volatile("cp.async.commit_group;" ::: "memory");
    };

    const int wid  = tid >> 5;
    const int lane = tid & 31;
    const int gID  = lane >> 2;
    const int tig  = lane & 3;
    const int wm   = (wid >> 1) * 32;
    const int wn   = (wid & 1) * 64;

    float c[2][8][4];
#pragma unroll
    for (int i = 0; i < 2; i++)
#pragma unroll
        for (int j = 0; j < 8; j++)
#pragma unroll
            for (int q = 0; q < 4; q++) c[i][j][q] = 0.0f;

    fill(0, 0);

    for (int ch = 0; ch < NC; ch++) {
        if (ch + 1 < NC) {
            fill(ch + 1, (ch + 1) & 1);
            asm volatile("cp.async.wait_group 1;" ::: "memory");
        } else {
            asm volatile("cp.async.wait_group 0;" ::: "memory");
        }
        __syncthreads();

        const u32* As = sm32 + (ch & 1) * 2 * TBUF;
        const u32* Bs = As + TBUF;

#pragma unroll
        for (int ks = 0; ks < KC / 16; ks++) {
            const int kw = ks * 8;
            u32 a[2][4];
#pragma unroll
            for (int mi = 0; mi < 2; mi++) {
                int r = wm + mi * 16 + gID;
                a[mi][0] = As[r * SKW + kw + tig];
                a[mi][1] = As[(r + 8) * SKW + kw + tig];
                a[mi][2] = As[r * SKW + kw + tig + 4];
                a[mi][3] = As[(r + 8) * SKW + kw + tig + 4];
            }
            u32 b[8][2];
#pragma unroll
            for (int ni = 0; ni < 8; ni++) {
                int r = wn + ni * 8 + gID;
                b[ni][0] = Bs[r * SKW + kw + tig];
                b[ni][1] = Bs[r * SKW + kw + tig + 4];
            }
#pragma unroll
            for (int mi = 0; mi < 2; mi++)
#pragma unroll
                for (int ni = 0; ni < 8; ni++)
                    mma_f16(c[mi][ni][0], c[mi][ni][1], c[mi][ni][2], c[mi][ni][3],
                            a[mi][0], a[mi][1], a[mi][2], a[mi][3],
                            b[ni][0], b[ni][1]);
        }
        __syncthreads();
    }

#pragma unroll
    for (int ni = 0; ni < 8; ni++) {
        int g = nt * 128 + wn + ni * 8 + 2 * tig;
        float2 bv = *(const float2*)&bsum[g];
#pragma unroll
        for (int mi = 0; mi < 2; mi++) {
            size_t m = (size_t)mt * 128 + wm + mi * 16 + gID;
            *(__half2*)&out[m * Gd + g] =
                __floats2half2_rn(c[mi][ni][0] + bv.x, c[mi][ni][1] + bv.y);
            *(__half2*)&out[(m + 8) * Gd + g] =
                __floats2half2_rn(c[mi][ni][2] + bv.x, c[mi][ni][3] + bv.y);
        }
    }
}

// ---------------------------------------------------------------------------
// LSTM recurrence v4: ALL weights in registers as fp16 half2 pairs
// (2 cols x 64 half2 = 128 u32 regs) -> ZERO smem weight traffic.
// h double-buffered fp16 in smem (16 broadcast LDS.128 per batch per step).
// hfma2 with 4 interleaved chains per gate (32 terms each), fp32 final sums,
// fp32 cell/activations. One barrier per step.
// ---------------------------------------------------------------------------
#define HROW 144                              // padded halves per batch row
#define SMEM_REC (2 * 2 * HROW * 2)           // 1152 B

template <bool YIMG>
__global__ __launch_bounds__(REC_THREADS, 1) void lstm_rec_kernel(
    const __half* __restrict__ xg, const float* __restrict__ Whh,
    __half* __restrict__ y_img, float* __restrict__ y_last)
{
    extern __shared__ char smraw[];
    __half* hb = (__half*)smraw;              // [2 phase][2 batch][HROW]

    const int t = threadIdx.x;
    const int u = t >> 1;
    const int p = t & 1;
    const int col0 = p * 128 + u;             // i (p=0) / f (p=1)
    const int col1 = 256 + p * 128 + u;       // g (p=0) / o (p=1)
    const int b0 = blockIdx.x * 2;

    // Full weight rows in registers, fp16 pairs: 64 half2 per column.
    u32 wA2[64], wB2[64];
#pragma unroll
    for (int j = 0; j < 64; j++) {
        __half2 a = __floats2half2_rn(Whh[(size_t)col0 * Hd + 2 * j],
                                      Whh[(size_t)col0 * Hd + 2 * j + 1]);
        __half2 b = __floats2half2_rn(Whh[(size_t)col1 * Hd + 2 * j],
                                      Whh[(size_t)col1 * Hd + 2 * j + 1]);
        wA2[j] = *(u32*)&a;
        wB2[j] = *(u32*)&b;
    }
    for (int i = t; i < 2 * 2 * HROW; i += REC_THREADS) hb[i] = __half(0.0f);

    float c = 0.0f;
    __syncthreads();

    __half xh00 = xg[(size_t)(b0)*Gd + col0];
    __half xh01 = xg[(size_t)(b0 + 1) * Gd + col0];
    __half xh10 = xg[(size_t)(b0)*Gd + col1];
    __half xh11 = xg[(size_t)(b0 + 1) * Gd + col1];

    for (int s = 0; s < Sd; s++) {
        __half nh00, nh01, nh10, nh11;
        if (s + 1 < Sd) {
            size_t base = (size_t)(s + 1) * Bd + b0;
            nh00 = xg[base * Gd + col0];
            nh01 = xg[(base + 1) * Gd + col0];
            nh10 = xg[base * Gd + col1];
            nh11 = xg[(base + 1) * Gd + col1];
        } else {
            nh00 = nh01 = nh10 = nh11 = __half(0.0f);
        }
        const int ph = s & 1;
        const ulonglong2* hq0 = (const ulonglong2*)(hb + (ph * 2 + 0) * HROW);
        const ulonglong2* hq1 = (const ulonglong2*)(hb + (ph * 2 + 1) * HROW);

        // 4 interleaved half2 chains per gate-batch combo (32 terms each)
        __half2 z = __floats2half2_rn(0.0f, 0.0f);
        __half2 aA0[4] = {z, z, z, z}, aA1[4] = {z, z, z, z};
        __half2 aB0[4] = {z, z, z, z}, aB1[4] = {z, z, z, z};

#pragma unroll
        for (int q = 0; q < 16; q++) {        // 16B quads: 4 half2 each
            ulonglong2 q0 = hq0[q];
            ulonglong2 q1 = hq1[q];
            const __half2* h0 = (const __half2*)&q0;
            const __half2* h1 = (const __half2*)&q1;
#pragma unroll
            for (int j2 = 0; j2 < 4; j2++) {
                const int wi = q * 4 + j2;
                const int chn = wi & 3;
                __half2 w0 = *(const __half2*)&wA2[wi];
                __half2 w1 = *(const __half2*)&wB2[wi];
                aA0[chn] = __hfma2(w0, h0[j2], aA0[chn]);
                aA1[chn] = __hfma2(w0, h1[j2], aA1[chn]);
                aB0[chn] = __hfma2(w1, h0[j2], aB0[chn]);
                aB1[chn] = __hfma2(w1, h1[j2], aB1[chn]);
            }
        }

        // fp32 reduction of the chains
        float2 fA0a = __half22float2(aA0[0]), fA0b = __half22float2(aA0[1]);
        float2 fA0c = __half22float2(aA0[2]), fA0d = __half22float2(aA0[3]);
        float2 fA1a = __half22float2(aA1[0]), fA1b = __half22float2(aA1[1]);
        float2 fA1c = __half22float2(aA1[2]), fA1d = __half22float2(aA1[3]);
        float2 fB0a = __half22float2(aB0[0]), fB0b = __half22float2(aB0[1]);
        float2 fB0c = __half22float2(aB0[2]), fB0d = __half22float2(aB0[3]);
        float2 fB1a = __half22float2(aB1[0]), fB1b = __half22float2(aB1[1]);
        float2 fB1c = __half22float2(aB1[2]), fB1d = __half22float2(aB1[3]);

        float p00 = __half2float(xh00) +
            ((fA0a.x + fA0a.y) + (fA0b.x + fA0b.y)) +
            ((fA0c.x + fA0c.y) + (fA0d.x + fA0d.y));
        float p01 = __half2float(xh01) +
            ((fA1a.x + fA1a.y) + (fA1b.x + fA1b.y)) +
            ((fA1c.x + fA1c.y) + (fA1d.x + fA1d.y));
        float p10 = __half2float(xh10) +
            ((fB0a.x + fB0a.y) + (fB0b.x + fB0b.y)) +
            ((fB0c.x + fB0c.y) + (fB0d.x + fB0d.y));
        float p11 = __half2float(xh11) +
            ((fB1a.x + fB1a.y) + (fB1b.x + fB1b.y)) +
            ((fB1c.x + fB1c.y) + (fB1d.x + fB1d.y));

        float v00 = fmaf(0.5f, tanh_fast(0.5f * p00), 0.5f);
        float v01 = fmaf(0.5f, tanh_fast(0.5f * p01), 0.5f);
        float a10s = (p == 0) ? p10 : 0.5f * p10;
        float a11s = (p == 0) ? p11 : 0.5f * p11;
        float t10 = tanh_fast(a10s);
        float t11 = tanh_fast(a11s);
        float v10 = (p == 0) ? t10 : fmaf(0.5f, t10, 0.5f);
        float v11 = (p == 0) ? t11 : fmaf(0.5f, t11, 0.5f);

        float send1 = (p == 0) ? v01 : v00;
        float send2 = (p == 0) ? v11 : v10;
        float got1 = __shfl_xor_sync(0xffffffffu, send1, 1);
        float got2 = __shfl_xor_sync(0xffffffffu, send2, 1);

        float iv = (p == 0) ? v00 : got1;
        float fv = (p == 0) ? got1 : v01;
        float gv = (p == 0) ? v10 : got2;
        float ov = (p == 0) ? got2 : v11;

        c = fmaf(fv, c, iv * gv);
        float hn = ov * tanh_fast(c);

        __half hn16 = __float2half(hn);
        hb[((ph ^ 1) * 2 + p) * HROW + u] = hn16;
        if (YIMG) {
            y_img[((size_t)s * Bd + b0 + p) * Hd + u] = hn16;
        } else if (s == Sd - 1) {
            y_last[(size_t)(b0 + p) * Hd + u] = hn;
        }

        xh00 = nh00; xh01 = nh01; xh10 = nh10; xh11 = nh11;
        __syncthreads();
    }
}

// ---------------------------------------------------------------------------
extern "C" void kernel_launch(void* const* d_in, const int* in_sizes, int n_in,
                              void* d_out, int out_size)
{
    const float* x    = (const float*)d_in[0];
    const float* Wih0 = (const float*)d_in[1];
    const float* Whh0 = (const float*)d_in[2];
    const float* bih0 = (const float*)d_in[3];
    const float* bhh0 = (const float*)d_in[4];
    const float* Wih1 = (const float*)d_in[5];
    const float* Whh1 = (const float*)d_in[6];
    const float* bih1 = (const float*)d_in[7];
    const float* bhh1 = (const float*)d_in[8];
    float* out = (float*)d_out;

    __half *xg, *a0, *y1h, *w0h, *w1h;
    float *bs0, *bs1;
    cudaGetSymbolAddress((void**)&xg, g_xg);
    cudaGetSymbolAddress((void**)&a0, g_a0);
    cudaGetSymbolAddress((void**)&y1h, g_y1h);
    cudaGetSymbolAddress((void**)&w0h, g_w0h);
    cudaGetSymbolAddress((void**)&w1h, g_w1h);
    cudaGetSymbolAddress((void**)&bs0, g_bs0);
    cudaGetSymbolAddress((void**)&bs1, g_bs1);

    const int smem_gemm = 2 * 2 * 128 * 20 * 4;   // 40960 B

    cudaFuncSetAttribute((const void*)gemm_f16_kernel<Cd>,
                         cudaFuncAttributeMaxDynamicSharedMemorySize, smem_gemm);
    cudaFuncSetAttribute((const void*)gemm_f16_kernel<Hd>,
                         cudaFuncAttributeMaxDynamicSharedMemorySize, smem_gemm);
    cudaFuncSetAttribute((const void*)lstm_rec_kernel<true>,
                         cudaFuncAttributeMaxDynamicSharedMemorySize, SMEM_REC);
    cudaFuncSetAttribute((const void*)lstm_rec_kernel<false>,
                         cudaFuncAttributeMaxDynamicSharedMemorySize, SMEM_REC);

    prep_x_kernel<<<(Bd * Sd * Cd + 255) / 256, 256>>>(x);
    prep_w_kernel<<<(Gd * Cd + 255) / 256, 256>>>(Wih0, bih0, bhh0, w0h, bs0, Gd * Cd);
    prep_w_kernel<<<(Gd * Hd + 255) / 256, 256>>>(Wih1, bih1, bhh1, w1h, bs1, Gd * Hd);

    dim3 ggrid((Sd * Bd) / 128, Gd / 128);

    // layer 0
    gemm_f16_kernel<Cd><<<ggrid, 256, smem_gemm>>>(a0, w0h, bs0, xg);
    lstm_rec_kernel<true><<<Bd / 2, REC_THREADS, SMEM_REC>>>(xg, Whh0, y1h, nullptr);

    // layer 1
    gemm_f16_kernel<Hd><<<ggrid, 256, smem_gemm>>>(y1h, w1h, bs1, xg);
    lstm_rec_kernel<false><<<Bd / 2, REC_THREADS, SMEM_REC>>>(xg, Whh1, nullptr, out);
}

// round 16
// speedup vs baseline: 1.4163x; 1.2805x over previous
#include <cuda_runtime.h>
#include <cuda_fp16.h>
#include <cstdint>

#define Bd 256
#define Sd 512
#define Cd 64
#define Hd 128
#define Gd 512
#define REC_THREADS 512

typedef unsigned long long u64;
typedef unsigned int u32;

// ---------------- device global scratch ----------------
__device__ __half g_xg[(size_t)Sd * Bd * Gd];     // gate preacts, fp16
__device__ __half g_a0[(size_t)Sd * Bd * Cd];     // x, fp16, m-major
__device__ __half g_y1h[(size_t)Sd * Bd * Hd];    // layer-0 h, fp16, m-major
__device__ __half g_w0h[(size_t)Gd * Cd];         // Wih0 fp16
__device__ __half g_w1h[(size_t)Gd * Hd];         // Wih1 fp16
__device__ float  g_bs0[Gd];
__device__ float  g_bs1[Gd];

// ---------------- helpers ----------------
__device__ __forceinline__ float tanh_fast(float x) {
    float y; asm("tanh.approx.f32 %0, %1;" : "=f"(y) : "f"(x)); return y;
}
__device__ __forceinline__ void mma_f16(
    float& c0, float& c1, float& c2, float& c3,
    u32 a0, u32 a1, u32 a2, u32 a3, u32 b0, u32 b1)
{
    asm("mma.sync.aligned.m16n8k16.row.col.f32.f16.f16.f32 "
        "{%0,%1,%2,%3}, {%4,%5,%6,%7}, {%8,%9}, {%0,%1,%2,%3};"
        : "+f"(c0), "+f"(c1), "+f"(c2), "+f"(c3)
        : "r"(a0), "r"(a1), "r"(a2), "r"(a3), "r"(b0), "r"(b1));
}
__device__ __forceinline__ void cp16(u32 dst, const void* src) {
    asm volatile("cp.async.cg.shared.global [%0], [%1], 16;" :: "r"(dst), "l"(src));
}
__device__ __forceinline__ u32 smem_u32(const void* p) {
    u32 a; asm("{ .reg .u64 t; cvta.to.shared.u64 t, %1; cvt.u32.u64 %0, t; }" : "=r"(a) : "l"(p));
    return a;
}

// ---------------- prep kernels ----------------
__global__ void prep_x_kernel(const float* __restrict__ x)
{
    int i = blockIdx.x * 256 + threadIdx.x;
    if (i >= Bd * Sd * Cd) return;
    int k = i & (Cd - 1);
    int s = (i >> 6) & (Sd - 1);
    int b = i >> 15;
    g_a0[((size_t)(s * Bd + b)) * Cd + k] = __float2half(x[i]);
}

__global__ void prep_w_kernel(const float* __restrict__ W, const float* __restrict__ b1,
                              const float* __restrict__ b2, __half* __restrict__ wh,
                              float* __restrict__ bsum, int n)
{
    int i = blockIdx.x * 256 + threadIdx.x;
    if (i >= n) return;
    wh[i] = __float2half(W[i]);
    if (i < Gd) bsum[i] = b1[i] + b2[i];
}

// ---------------------------------------------------------------------------
// Pipelined FP16 GEMM (fp32 accum) — unchanged (round-13 proven).
// ---------------------------------------------------------------------------
template <int K>
__global__ __launch_bounds__(256) void gemm_f16_kernel(
    const __half* __restrict__ A, const __half* __restrict__ Wh,
    const float* __restrict__ bsum, __half* __restrict__ out)
{
    constexpr int KC = 32;
    constexpr int NC = K / KC;
    constexpr int SKW = 20;
    constexpr int TBUF = 128 * SKW;

    extern __shared__ u32 sm32[];
    const u32 sb = smem_u32(sm32);

    const int tid = threadIdx.x;
    const int mt  = blockIdx.x;
    const int nt  = blockIdx.y;

    auto fill = [&](int c, int buf) {
        const int k0 = c * KC;
#pragma unroll
        for (int r = 0; r < 2; r++) {
            int task = tid + 256 * r;
            int row = task >> 2, seg = task & 3;
            cp16(sb + (u32)(buf * 2 * TBUF + row * SKW + seg * 4) * 4,
                 (const char*)(A + (size_t)(mt * 128 + row) * K + k0) + seg * 16);
        }
#pragma unroll
        for (int r = 0; r < 2; r++) {
            int task = tid + 256 * r;
            int row = task >> 2, seg = task & 3;
            cp16(sb + (u32)(buf * 2 * TBUF + TBUF + row * SKW + seg * 4) * 4,
                 (const char*)(Wh + (size_t)(nt * 128 + row) * K + k0) + seg * 16);
        }
        asm volatile("cp.async.commit_group;" ::: "memory");
    };

    const int wid  = tid >> 5;
    const int lane = tid & 31;
    const int gID  = lane >> 2;
    const int tig  = lane & 3;
    const int wm   = (wid >> 1) * 32;
    const int wn   = (wid & 1) * 64;

    float c[2][8][4];
#pragma unroll
    for (int i = 0; i < 2; i++)
#pragma unroll
        for (int j = 0; j < 8; j++)
#pragma unroll
            for (int q = 0; q < 4; q++) c[i][j][q] = 0.0f;

    fill(0, 0);

    for (int ch = 0; ch < NC; ch++) {
        if (ch + 1 < NC) {
            fill(ch + 1, (ch + 1) & 1);
            asm volatile("cp.async.wait_group 1;" ::: "memory");
        } else {
            asm volatile("cp.async.wait_group 0;" ::: "memory");
        }
        __syncthreads();

        const u32* As = sm32 + (ch & 1) * 2 * TBUF;
        const u32* Bs = As + TBUF;

#pragma unroll
        for (int ks = 0; ks < KC / 16; ks++) {
            const int kw = ks * 8;
            u32 a[2][4];
#pragma unroll
            for (int mi = 0; mi < 2; mi++) {
                int r = wm + mi * 16 + gID;
                a[mi][0] = As[r * SKW + kw + tig];
                a[mi][1] = As[(r + 8) * SKW + kw + tig];
                a[mi][2] = As[r * SKW + kw + tig + 4];
                a[mi][3] = As[(r + 8) * SKW + kw + tig + 4];
            }
            u32 b[8][2];
#pragma unroll
            for (int ni = 0; ni < 8; ni++) {
                int r = wn + ni * 8 + gID;
                b[ni][0] = Bs[r * SKW + kw + tig];
                b[ni][1] = Bs[r * SKW + kw + tig + 4];
            }
#pragma unroll
            for (int mi = 0; mi < 2; mi++)
#pragma unroll
                for (int ni = 0; ni < 8; ni++)
                    mma_f16(c[mi][ni][0], c[mi][ni][1], c[mi][ni][2], c[mi][ni][3],
                            a[mi][0], a[mi][1], a[mi][2], a[mi][3],
                            b[ni][0], b[ni][1]);
        }
        __syncthreads();
    }

#pragma unroll
    for (int ni = 0; ni < 8; ni++) {
        int g = nt * 128 + wn + ni * 8 + 2 * tig;
        float2 bv = *(const float2*)&bsum[g];
#pragma unroll
        for (int mi = 0; mi < 2; mi++) {
            size_t m = (size_t)mt * 128 + wm + mi * 16 + gID;
            *(__half2*)&out[m * Gd + g] =
                __floats2half2_rn(c[mi][ni][0] + bv.x, c[mi][ni][1] + bv.y);
            *(__half2*)&out[(m + 8) * Gd + g] =
                __floats2half2_rn(c[mi][ni][2] + bv.x, c[mi][ni][3] + bv.y);
        }
    }
}

// ---------------------------------------------------------------------------
// LSTM recurrence v5: 512 threads (4 warps/SMSP for latency hiding).
// Quad {4u..4u+3} owns gates {i,f,g,o} of unit u (thread r = gate index).
// Weights: 1 column fully in registers as 64 fp16 half2 (64 regs).
// h double-buffered fp16 in smem; hfma2 4-chain accumulation per batch;
// fp32 reductions, fp32 cell; quad-shfl epilogue; ONE barrier per step.
// ---------------------------------------------------------------------------
#define HROW 144
#define SMEM_REC (2 * 2 * HROW * 2)           // 1152 B

template <bool YIMG>
__global__ __launch_bounds__(REC_THREADS, 1) void lstm_rec_kernel(
    const __half* __restrict__ xg, const float* __restrict__ Whh,
    __half* __restrict__ y_img, float* __restrict__ y_last)
{
    extern __shared__ char smraw[];
    __half* hb = (__half*)smraw;              // [2 phase][2 batch][HROW]

    const int t = threadIdx.x;
    const int r = t & 3;                      // gate index (0=i,1=f,2=g,3=o)
    const int u = t >> 2;                     // hidden unit
    const int col = r * Hd + u;               // gate column in xg / Whh row
    const int b0 = blockIdx.x * 2;
    const int qb = (t & 31) & ~3;             // quad base lane

    // Full weight row in registers: 64 fp16 pairs.
    u32 w2[64];
#pragma unroll
    for (int j = 0; j < 64; j++) {
        __half2 a = __floats2half2_rn(Whh[(size_t)col * Hd + 2 * j],
                                      Whh[(size_t)col * Hd + 2 * j + 1]);
        w2[j] = *(u32*)&a;
    }
    for (int i = t; i < 2 * 2 * HROW; i += REC_THREADS) hb[i] = __half(0.0f);

    float c = 0.0f;
    __syncthreads();

    __half xh0 = xg[(size_t)(b0)*Gd + col];
    __half xh1 = xg[(size_t)(b0 + 1) * Gd + col];

    for (int s = 0; s < Sd; s++) {
        __half nx0, nx1;
        if (s + 1 < Sd) {
            size_t base = (size_t)(s + 1) * Bd + b0;
            nx0 = xg[base * Gd + col];
            nx1 = xg[(base + 1) * Gd + col];
        } else {
            nx0 = nx1 = __half(0.0f);
        }
        const int ph = s & 1;
        const ulonglong2* hq0 = (const ulonglong2*)(hb + (ph * 2 + 0) * HROW);
        const ulonglong2* hq1 = (const ulonglong2*)(hb + (ph * 2 + 1) * HROW);

        // 4 interleaved half2 chains per batch (16 terms each)
        __half2 z = __floats2half2_rn(0.0f, 0.0f);
        __half2 a0[4] = {z, z, z, z};
        __half2 a1[4] = {z, z, z, z};

#pragma unroll
        for (int q = 0; q < 16; q++) {        // 16B quads: 4 half2 each
            ulonglong2 q0 = hq0[q];
            ulonglong2 q1 = hq1[q];
            const __half2* h0 = (const __half2*)&q0;
            const __half2* h1 = (const __half2*)&q1;
#pragma unroll
            for (int j2 = 0; j2 < 4; j2++) {
                __half2 w = *(const __half2*)&w2[q * 4 + j2];
                a0[j2] = __hfma2(w, h0[j2], a0[j2]);
                a1[j2] = __hfma2(w, h1[j2], a1[j2]);
            }
        }

        float2 f0a = __half22float2(a0[0]), f0b = __half22float2(a0[1]);
        float2 f0c = __half22float2(a0[2]), f0d = __half22float2(a0[3]);
        float2 f1a = __half22float2(a1[0]), f1b = __half22float2(a1[1]);
        float2 f1c = __half22float2(a1[2]), f1d = __half22float2(a1[3]);

        float p0 = __half2float(xh0) +
            ((f0a.x + f0a.y) + (f0b.x + f0b.y)) +
            ((f0c.x + f0c.y) + (f0d.x + f0d.y));
        float p1 = __half2float(xh1) +
            ((f1a.x + f1a.y) + (f1b.x + f1b.y)) +
            ((f1c.x + f1c.y) + (f1d.x + f1d.y));

        // activation: r==2 (g gate) tanh, else sigmoid
        float s0 = (r == 2) ? p0 : 0.5f * p0;
        float s1 = (r == 2) ? p1 : 0.5f * p1;
        float t0 = tanh_fast(s0);
        float t1 = tanh_fast(s1);
        float v0 = (r == 2) ? t0 : fmaf(0.5f, t0, 0.5f);
        float v1 = (r == 2) ? t1 : fmaf(0.5f, t1, 0.5f);

        // quad transpose via shfl (i,f,g,o for both batches)
        float i0 = __shfl_sync(0xffffffffu, v0, qb + 0);
        float ff0 = __shfl_sync(0xffffffffu, v0, qb + 1);
        float gg0 = __shfl_sync(0xffffffffu, v0, qb + 2);
        float o0 = __shfl_sync(0xffffffffu, v0, qb + 3);
        float i1 = __shfl_sync(0xffffffffu, v1, qb + 0);
        float ff1 = __shfl_sync(0xffffffffu, v1, qb + 1);
        float gg1 = __shfl_sync(0xffffffffu, v1, qb + 2);
        float o1 = __shfl_sync(0xffffffffu, v1, qb + 3);

        // lane r==0 owns batch0; lane r==1 owns batch1
        float iv = (r == 0) ? i0 : i1;
        float fv = (r == 0) ? ff0 : ff1;
        float gv = (r == 0) ? gg0 : gg1;
        float ov = (r == 0) ? o0 : o1;
        c = fmaf(fv, c, iv * gv);
        float hn = ov * tanh_fast(c);

        if (r < 2) {
            __half hn16 = __float2half(hn);
            hb[((ph ^ 1) * 2 + r) * HROW + u] = hn16;
            if (YIMG) {
                y_img[((size_t)s * Bd + b0 + r) * Hd + u] = hn16;
            } else if (s == Sd - 1) {
                y_last[(size_t)(b0 + r) * Hd + u] = hn;
            }
        }

        xh0 = nx0; xh1 = nx1;
        __syncthreads();
    }
}

// ---------------------------------------------------------------------------
extern "C" void kernel_launch(void* const* d_in, const int* in_sizes, int n_in,
                              void* d_out, int out_size)
{
    const float* x    = (const float*)d_in[0];
    const float* Wih0 = (const float*)d_in[1];
    const float* Whh0 = (const float*)d_in[2];
    const float* bih0 = (const float*)d_in[3];
    const float* bhh0 = (const float*)d_in[4];
    const float* Wih1 = (const float*)d_in[5];
    const float* Whh1 = (const float*)d_in[6];
    const float* bih1 = (const float*)d_in[7];
    const float* bhh1 = (const float*)d_in[8];
    float* out = (float*)d_out;

    __half *xg, *a0, *y1h, *w0h, *w1h;
    float *bs0, *bs1;
    cudaGetSymbolAddress((void**)&xg, g_xg);
    cudaGetSymbolAddress((void**)&a0, g_a0);
    cudaGetSymbolAddress((void**)&y1h, g_y1h);
    cudaGetSymbolAddress((void**)&w0h, g_w0h);
    cudaGetSymbolAddress((void**)&w1h, g_w1h);
    cudaGetSymbolAddress((void**)&bs0, g_bs0);
    cudaGetSymbolAddress((void**)&bs1, g_bs1);

    const int smem_gemm = 2 * 2 * 128 * 20 * 4;   // 40960 B

    cudaFuncSetAttribute((const void*)gemm_f16_kernel<Cd>,
                         cudaFuncAttributeMaxDynamicSharedMemorySize, smem_gemm);
    cudaFuncSetAttribute((const void*)gemm_f16_kernel<Hd>,
                         cudaFuncAttributeMaxDynamicSharedMemorySize, smem_gemm);
    cudaFuncSetAttribute((const void*)lstm_rec_kernel<true>,
                         cudaFuncAttributeMaxDynamicSharedMemorySize, SMEM_REC);
    cudaFuncSetAttribute((const void*)lstm_rec_kernel<false>,
                         cudaFuncAttributeMaxDynamicSharedMemorySize, SMEM_REC);

    prep_x_kernel<<<(Bd * Sd * Cd + 255) / 256, 256>>>(x);
    prep_w_kernel<<<(Gd * Cd + 255) / 256, 256>>>(Wih0, bih0, bhh0, w0h, bs0, Gd * Cd);
    prep_w_kernel<<<(Gd * Hd + 255) / 256, 256>>>(Wih1, bih1, bhh1, w1h, bs1, Gd * Hd);

    dim3 ggrid((Sd * Bd) / 128, Gd / 128);

    // layer 0
    gemm_f16_kernel<Cd><<<ggrid, 256, smem_gemm>>>(a0, w0h, bs0, xg);
    lstm_rec_kernel<true><<<Bd / 2, REC_THREADS, SMEM_REC>>>(xg, Whh0, y1h, nullptr);

    // layer 1
    gemm_f16_kernel<Hd><<<ggrid, 256, smem_gemm>>>(y1h, w1h, bs1, xg);
    lstm_rec_kernel<false><<<Bd / 2, REC_THREADS, SMEM_REC>>>(xg, Whh1, nullptr, out);
}